// round 11
// baseline (speedup 1.0000x reference)
#include <cuda_runtime.h>
#include <cuda_fp16.h>
#include <math.h>
#include <cstdint>

#define BB     2
#define NTOK   4096
#define DIM    768
#define HEADS  12
#define HD     64
#define HID    1536
#define HINTR  1024

// ---------------- device scratch ----------------
__device__ int    g_edge[BB*NTOK];
__device__ int    g_cntE[BB];
__device__ int    g_cntZ[BB];
__device__ int    g_eidx[BB*NTOK];
__device__ int    g_zidx[BB*NTOK];
__device__ __half g_xh [(size_t)BB*NTOK*DIM];
__device__ __half g_wqkv[(size_t)DIM*3*DIM];
__device__ __half g_wproj[(size_t)DIM*DIM];
__device__ __half g_wfc1[(size_t)DIM*HID];
__device__ __half g_wfc2[(size_t)HID*DIM];
__device__ __half g_qh [(size_t)BB*HEADS*NTOK*HD];
__device__ __half g_kh [(size_t)BB*HEADS*NTOK*HD];
__device__ __half g_vh [(size_t)BB*HEADS*NTOK*HD];
__device__ __half g_oh [(size_t)BB*NTOK*DIM];
__device__ __half g_hln[(size_t)BB*NTOK*DIM];
__device__ __half g_h1 [(size_t)BB*NTOK*HID];
__device__ float  g_h2 [(size_t)BB*NTOK*DIM];
__device__ float  g_poolp[BB*16*DIM];
__device__ float  g_sig [BB*DIM];

// ---------------- asm helpers ----------------
__device__ __forceinline__ void mma16(float4& d, const unsigned* a, unsigned b0, unsigned b1) {
    asm volatile(
        "mma.sync.aligned.m16n8k16.row.col.f32.f16.f16.f32 "
        "{%0,%1,%2,%3}, {%4,%5,%6,%7}, {%8,%9}, {%0,%1,%2,%3};\n"
        : "+f"(d.x), "+f"(d.y), "+f"(d.z), "+f"(d.w)
        : "r"(a[0]), "r"(a[1]), "r"(a[2]), "r"(a[3]), "r"(b0), "r"(b1));
}
__device__ __forceinline__ void ldsm4(unsigned* r, const void* p) {
    unsigned a = (unsigned)__cvta_generic_to_shared(p);
    asm volatile("ldmatrix.sync.aligned.m8n8.x4.shared.b16 {%0,%1,%2,%3}, [%4];\n"
        : "=r"(r[0]), "=r"(r[1]), "=r"(r[2]), "=r"(r[3]) : "r"(a));
}
__device__ __forceinline__ void ldsm4t(unsigned* r, const void* p) {
    unsigned a = (unsigned)__cvta_generic_to_shared(p);
    asm volatile("ldmatrix.sync.aligned.m8n8.x4.trans.shared.b16 {%0,%1,%2,%3}, [%4];\n"
        : "=r"(r[0]), "=r"(r[1]), "=r"(r[2]), "=r"(r[3]) : "r"(a));
}
__device__ __forceinline__ void cpa16(void* smem, const void* gmem) {
    unsigned s = (unsigned)__cvta_generic_to_shared(smem);
    asm volatile("cp.async.cg.shared.global [%0], [%1], 16;\n" :: "r"(s), "l"(gmem));
}
__device__ __forceinline__ void cpa16z(void* smem, const void* gmem, bool pred) {
    unsigned s = (unsigned)__cvta_generic_to_shared(smem);
    int sz = pred ? 16 : 0;
    asm volatile("cp.async.cg.shared.global [%0], [%1], 16, %2;\n" :: "r"(s), "l"(gmem), "r"(sz));
}
__device__ __forceinline__ void cpa_commit() { asm volatile("cp.async.commit_group;\n"); }
__device__ __forceinline__ void cpa_wait2()  { asm volatile("cp.async.wait_group 2;\n"); }
__device__ __forceinline__ unsigned h2u(__half2 h) { return *(unsigned*)&h; }
__device__ __forceinline__ float ex2(float x) {
    float y; asm("ex2.approx.ftz.f32 %0, %1;" : "=f"(y) : "f"(x)); return y;
}

// ---------------- merged fp32 -> fp16 conversion ----------------
__global__ void k_cvtall(const float* __restrict__ x,  const float* __restrict__ w0,
                         const float* __restrict__ w1, const float* __restrict__ w2,
                         const float* __restrict__ w3) {
    int bx = blockIdx.x;
    const float* src; __half* dst; long base;
    if (bx < 3072)      { src = x;  dst = g_xh;    base = (long)bx * 2048; }
    else if (bx < 3936) { src = w0; dst = g_wqkv;  base = (long)(bx - 3072) * 2048; }
    else if (bx < 4224) { src = w1; dst = g_wproj; base = (long)(bx - 3936) * 2048; }
    else if (bx < 4800) { src = w2; dst = g_wfc1;  base = (long)(bx - 4224) * 2048; }
    else                { src = w3; dst = g_wfc2;  base = (long)(bx - 4800) * 2048; }
    long i = base + threadIdx.x * 8;
    float4 f0 = *(const float4*)(src + i);
    float4 f1 = *(const float4*)(src + i + 4);
    __half2 h[4] = { __floats2half2_rn(f0.x, f0.y), __floats2half2_rn(f0.z, f0.w),
                     __floats2half2_rn(f1.x, f1.y), __floats2half2_rn(f1.z, f1.w) };
    *(uint4*)(dst + i) = *(uint4*)h;
}

// ---------------- edge mask ----------------
__global__ void k_edge(const float* __restrict__ hint) {
    int warp = threadIdx.x >> 5, lane = threadIdx.x & 31;
    int token = blockIdx.x * 8 + warp;
    int b = token / NTOK, t = token % NTOK;
    int ty = t >> 6, tx = t & 63;
    const float* base = hint + (size_t)b*HINTR*HINTR + (size_t)(ty*16)*HINTR + tx*16;
    int r = lane >> 1, half = lane & 1;
    const float4* p = (const float4*)(base + (size_t)r*HINTR + half*8);
    float4 a = p[0], c = p[1];
    float s = a.x+a.y+a.z+a.w + c.x+c.y+c.z+c.w;
    #pragma unroll
    for (int off = 16; off; off >>= 1) s += __shfl_down_sync(0xffffffffu, s, off);
    if (lane == 0) {
        float mean = s * (1.0f/256.0f);
        g_edge[token] = (mean > 0.02f && mean < 0.98f) ? 1 : 0;
    }
}

// ---------------- compaction with folded fallback ----------------
__global__ void k_compact() {
    int b = blockIdx.x, tid = threadIdx.x;
    int t0 = tid * 4;
    int f[4]; int e = 0;
    #pragma unroll
    for (int i = 0; i < 4; i++) { f[i] = g_edge[b*NTOK + t0 + i]; e += f[i]; }
    int lane = tid & 31, wid = tid >> 5;
    int v = e;
    #pragma unroll
    for (int off = 1; off < 32; off <<= 1) {
        int n = __shfl_up_sync(0xffffffffu, v, off);
        if (lane >= off) v += n;
    }
    __shared__ int wsum[32];
    if (lane == 31) wsum[wid] = v;
    __syncthreads();
    if (wid == 0) {
        int wv = wsum[lane];
        #pragma unroll
        for (int off = 1; off < 32; off <<= 1) {
            int n = __shfl_up_sync(0xffffffffu, wv, off);
            if (lane >= off) wv += n;
        }
        wsum[lane] = wv;
    }
    __syncthreads();
    int tot = wsum[31];
    if (tot < 64) {
        #pragma unroll
        for (int i = 0; i < 4; i++) g_eidx[b*NTOK + t0 + i] = t0 + i;
        if (tid == 1023) { g_cntE[b] = NTOK; g_cntZ[b] = 0; }
        return;
    }
    int excl = v - e + (wid ? wsum[wid-1] : 0);
    int eoff = excl, zoff = t0 - excl;
    #pragma unroll
    for (int i = 0; i < 4; i++) {
        if (f[i]) g_eidx[b*NTOK + eoff++] = t0 + i;
        else      g_zidx[b*NTOK + zoff++] = t0 + i;
    }
    if (tid == 1023) { g_cntE[b] = tot; g_cntZ[b] = NTOK - tot; }
}

// ---------------- fp16 MMA GEMM: 4-stage ring, wait_group 2 ----------------
__device__ __forceinline__ float gelu_exact(float x) {
    return 0.5f * x * (1.0f + erff(x * 0.70710678118654752f));
}

#define GEMM_SMEM (4*(128*40 + 32*136)*2)   // 75776 B

template<int EPI>
__global__ void __launch_bounds__(256)
k_gemm(const float* __restrict__ xfull, const __half* __restrict__ A,
       const __half* __restrict__ W, const float* __restrict__ bias,
       float* __restrict__ dout)
{
    constexpr int K = (EPI == 3) ? HID : DIM;
    constexpr int N = (EPI == 0) ? 3*DIM : (EPI == 2 ? HID : DIM);
    constexpr int NT = K / 32;
    const int* cntp = (EPI >= 2) ? g_cntZ : g_cntE;

    int b = blockIdx.z;
    int M = cntp[b];
    int m0 = blockIdx.y * 128;
    if (m0 >= M) return;
    int n0 = blockIdx.x * 128;
    const __half* Ab = A + (long)b * NTOK * K;

    extern __shared__ __align__(16) __half smg[];
    __half* As_ = smg;                   // 4 bufs x 128 x 40
    __half* Bs_ = smg + 4*128*40;        // 4 bufs x 32 x 136
    #define AS(bf,m,k)  As_[(bf)*5120 + (m)*40 + (k)]
    #define BS(bf,kr,n) Bs_[(bf)*4352 + (kr)*136 + (n)]

    int tid = threadIdx.x;
    int w = tid >> 5, lane = tid & 31;
    int wm = (w >> 2) * 64, wn = (w & 3) * 32;
    int qr = lane >> 2, qc = lane & 3;

    int  mA[2], cA[2], krB[2], cB[2];
    long arow[2];
    #pragma unroll
    for (int t = 0; t < 2; t++) {
        int task = tid + 256*t;
        mA[t] = task >> 2; cA[t] = (task & 3) * 8;
        int gm = m0 + mA[t];
        arow[t] = (gm < M) ? (long)((EPI == 0) ? g_eidx[b*NTOK + gm] : gm) * K : -1;
        krB[t] = task >> 4; cB[t] = (task & 15) * 8;
    }

    auto issue = [&](int k0, int bf) {
        #pragma unroll
        for (int t = 0; t < 2; t++) {
            const __half* asrc = (arow[t] >= 0) ? (Ab + arow[t] + k0 + cA[t]) : Ab;
            cpa16z(&AS(bf, mA[t], cA[t]), asrc, arow[t] >= 0);
            cpa16(&BS(bf, krB[t], cB[t]), W + (long)(k0 + krB[t])*N + n0 + cB[t]);
        }
    };

    float4 acc[4][4];
    #pragma unroll
    for (int i = 0; i < 4; i++)
        #pragma unroll
        for (int j = 0; j < 4; j++) acc[i][j] = make_float4(0,0,0,0);

    issue(0, 0);  cpa_commit();
    issue(32, 1); cpa_commit();
    issue(64, 2); cpa_commit();

    int bf = 0;
    #pragma unroll 1
    for (int it = 0; it < NT; it++) {
        cpa_wait2();
        __syncthreads();
        unsigned bfr[4][4];
        #pragma unroll
        for (int ni = 0; ni < 4; ni++)
            ldsm4t(bfr[ni], &BS(bf, lane, wn + ni*8));
        #pragma unroll
        for (int ks = 0; ks < 2; ks++) {
            unsigned afr[4][4];
            #pragma unroll
            for (int mi = 0; mi < 4; mi++)
                ldsm4(afr[mi], &AS(bf, wm + mi*16 + (lane & 15), ks*16 + (lane >> 4)*8));
            #pragma unroll
            for (int ni = 0; ni < 4; ni++)
                #pragma unroll
                for (int mi = 0; mi < 4; mi++)
                    mma16(acc[mi][ni], afr[mi], bfr[ni][ks*2], bfr[ni][ks*2+1]);
        }
        if (it + 3 < NT) {
            int nb = bf + 3; if (nb >= 4) nb -= 4;
            issue((it + 3) * 32, nb);
        }
        cpa_commit();
        if (++bf == 4) bf = 0;
    }

    #pragma unroll
    for (int mi = 0; mi < 4; mi++) {
        int rowA = m0 + wm + mi*16 + qr;
        int rowB = rowA + 8;
        #pragma unroll
        for (int ni = 0; ni < 4; ni++) {
            int col = n0 + wn + ni*8 + qc*2;
            float b0v = bias[col], b1v = bias[col+1];
            float vx = acc[mi][ni].x + b0v, vy = acc[mi][ni].y + b1v;
            float vz = acc[mi][ni].z + b0v, vw = acc[mi][ni].w + b1v;
            if (EPI == 0) {
                int part = col / DIM, cc = col - part*DIM;
                __half* dst = (part == 0) ? g_qh : (part == 1) ? g_kh : g_vh;
                int h = cc >> 6, d = cc & 63;
                long hb = ((long)b*HEADS + h)*NTOK;
                if (rowA < M) *(__half2*)&dst[(hb + rowA)*HD + d] = __floats2half2_rn(vx, vy);
                if (rowB < M) *(__half2*)&dst[(hb + rowB)*HD + d] = __floats2half2_rn(vz, vw);
            } else if (EPI == 1) {
                if (rowA < M) {
                    long o = ((long)b*NTOK + g_eidx[b*NTOK + rowA])*DIM + col;
                    *(float2*)&dout[o] = make_float2(vx + xfull[o], vy + xfull[o+1]);
                }
                if (rowB < M) {
                    long o = ((long)b*NTOK + g_eidx[b*NTOK + rowB])*DIM + col;
                    *(float2*)&dout[o] = make_float2(vz + xfull[o], vw + xfull[o+1]);
                }
            } else if (EPI == 2) {
                if (rowA < M) *(__half2*)&g_h1[((long)b*NTOK + rowA)*HID + col] =
                    __floats2half2_rn(gelu_exact(gelu_exact(vx)), gelu_exact(gelu_exact(vy)));
                if (rowB < M) *(__half2*)&g_h1[((long)b*NTOK + rowB)*HID + col] =
                    __floats2half2_rn(gelu_exact(gelu_exact(vz)), gelu_exact(gelu_exact(vw)));
            } else {
                if (rowA < M) *(float2*)&g_h2[((long)b*NTOK + rowA)*DIM + col] = make_float2(vx, vy);
                if (rowB < M) *(float2*)&g_h2[((long)b*NTOK + rowB)*DIM + col] = make_float2(vz, vw);
            }
        }
    }
    #undef AS
    #undef BS
}

// ---------------- fp16 flash attention: KT=64, 4-stage ring, wait_group 2 ----------------
#define KT 64
#define ATTN_SMEM (4*KT*72*2*2)   // 73728 B

__global__ void __launch_bounds__(256) k_attn() {
    int b = blockIdx.z, h = blockIdx.y;
    int M = g_cntE[b];
    int m0 = blockIdx.x * 128;
    if (m0 >= M) return;
    int tid = threadIdx.x, w = tid >> 5, lane = tid & 31;
    int qr = lane >> 2, qc = lane & 3;
    long base = ((long)b*HEADS + h)*NTOK*HD;

    extern __shared__ __align__(16) __half sma[];
    __half* Ks_ = sma;              // 4 x 64 x 72
    __half* Vs_ = sma + 4*KT*72;
    #define KS(bf,r,c) Ks_[(bf)*(KT*72) + (r)*72 + (c)]
    #define VS(bf,r,c) Vs_[(bf)*(KT*72) + (r)*72 + (c)]

    int r0 = m0 + w*16 + qr, r1 = r0 + 8;
    bool v0 = r0 < M, v1 = r1 < M;
    const __half* q0p = g_qh + base + (long)r0*HD;
    const __half* q1p = g_qh + base + (long)r1*HD;
    unsigned qf[4][4];
    #pragma unroll
    for (int ks = 0; ks < 4; ks++) {
        int c = ks*16 + qc*2;
        qf[ks][0] = v0 ? *(const unsigned*)&q0p[c]   : 0u;
        qf[ks][1] = v1 ? *(const unsigned*)&q1p[c]   : 0u;
        qf[ks][2] = v0 ? *(const unsigned*)&q0p[c+8] : 0u;
        qf[ks][3] = v1 ? *(const unsigned*)&q1p[c+8] : 0u;
    }

    auto issue = [&](int kb, int bf) {
        #pragma unroll
        for (int t = 0; t < 4; t++) {
            int task = tid + 256*t;            // 0..1023
            int mat  = task >> 9;
            int t2   = task & 511;
            int row  = t2 >> 3;
            int c8   = (t2 & 7) * 8;
            bool ok = (kb + row) < M;
            const __half* src = (mat ? g_vh : g_kh) + base + (long)(kb + (ok ? row : 0))*HD + c8;
            if (mat) cpa16z(&VS(bf, row, c8), src, ok);
            else     cpa16z(&KS(bf, row, c8), src, ok);
        }
    };

    float4 oacc[8];
    #pragma unroll
    for (int i = 0; i < 8; i++) oacc[i] = make_float4(0,0,0,0);
    float mx0 = -1e30f, mx1 = -1e30f, l0 = 0.0f, l1 = 0.0f;
    const float SC = 0.125f * 1.44269504088896340736f;

    int ntiles = (M + KT - 1) / KT;
    issue(0, 0); cpa_commit();
    if (ntiles > 1) issue(KT, 1);
    cpa_commit();
    if (ntiles > 2) issue(2*KT, 2);
    cpa_commit();

    int bf = 0;
    #pragma unroll 1
    for (int kt = 0; kt < ntiles; kt++) {
        int kb = kt * KT;
        cpa_wait2();
        __syncthreads();

        float4 s[8];
        #pragma unroll
        for (int nt = 0; nt < 8; nt++) s[nt] = make_float4(0,0,0,0);
        #pragma unroll
        for (int dh = 0; dh < 2; dh++) {
            #pragma unroll
            for (int nt = 0; nt < 8; nt++) {
                unsigned kf[4];
                ldsm4(kf, &KS(bf, nt*8 + (lane & 7), (lane >> 3)*8 + dh*32));
                mma16(s[nt], qf[dh*2],     kf[0], kf[1]);
                mma16(s[nt], qf[dh*2 + 1], kf[2], kf[3]);
            }
        }
        float t0 = -1e30f, t1 = -1e30f;
        #pragma unroll
        for (int nt = 0; nt < 8; nt++) {
            s[nt].x *= SC; s[nt].y *= SC; s[nt].z *= SC; s[nt].w *= SC;
            int c0 = kb + nt*8 + qc*2;
            if (c0     >= M) { s[nt].x = -1e30f; s[nt].z = -1e30f; }
            if (c0 + 1 >= M) { s[nt].y = -1e30f; s[nt].w = -1e30f; }
            t0 = fmaxf(t0, fmaxf(s[nt].x, s[nt].y));
            t1 = fmaxf(t1, fmaxf(s[nt].z, s[nt].w));
        }
        t0 = fmaxf(t0, __shfl_xor_sync(0xffffffffu, t0, 1));
        t0 = fmaxf(t0, __shfl_xor_sync(0xffffffffu, t0, 2));
        t1 = fmaxf(t1, __shfl_xor_sync(0xffffffffu, t1, 1));
        t1 = fmaxf(t1, __shfl_xor_sync(0xffffffffu, t1, 2));
        float nm0 = fmaxf(mx0, t0), nm1 = fmaxf(mx1, t1);
        bool nochg = (nm0 == mx0) && (nm1 == mx1);
        if (!__all_sync(0xffffffffu, nochg)) {
            float cr0 = ex2(mx0 - nm0), cr1 = ex2(mx1 - nm1);
            l0 *= cr0; l1 *= cr1;
            #pragma unroll
            for (int i = 0; i < 8; i++) {
                oacc[i].x *= cr0; oacc[i].y *= cr0;
                oacc[i].z *= cr1; oacc[i].w *= cr1;
            }
        }
        mx0 = nm0; mx1 = nm1;

        float ps0 = 0.0f, ps1 = 0.0f;
        unsigned pa[4][4];
        #pragma unroll
        for (int nt = 0; nt < 8; nt++) {
            float px = ex2(s[nt].x - mx0), py = ex2(s[nt].y - mx0);
            float pz = ex2(s[nt].z - mx1), pw = ex2(s[nt].w - mx1);
            ps0 += px + py; ps1 += pz + pw;
            int ks = nt >> 1, hi = (nt & 1) * 2;
            pa[ks][hi]     = h2u(__floats2half2_rn(px, py));
            pa[ks][hi + 1] = h2u(__floats2half2_rn(pz, pw));
        }
        ps0 += __shfl_xor_sync(0xffffffffu, ps0, 1);
        ps0 += __shfl_xor_sync(0xffffffffu, ps0, 2);
        ps1 += __shfl_xor_sync(0xffffffffu, ps1, 1);
        ps1 += __shfl_xor_sync(0xffffffffu, ps1, 2);
        l0 += ps0; l1 += ps1;

        #pragma unroll
        for (int ks = 0; ks < 4; ks++) {
            unsigned vf[4][4];
            #pragma unroll
            for (int dp = 0; dp < 4; dp++)
                ldsm4t(vf[dp], &VS(bf, 16*ks + ((lane >> 3) & 1)*8 + (lane & 7),
                                   dp*16 + (lane >> 4)*8));
            #pragma unroll
            for (int nt = 0; nt < 8; nt++)
                mma16(oacc[nt], pa[ks], vf[nt >> 1][(nt & 1)*2], vf[nt >> 1][(nt & 1)*2 + 1]);
        }

        if (kt + 3 < ntiles) {
            int nb = bf + 3; if (nb >= 4) nb -= 4;
            issue(kb + 3*KT, nb);
        }
        cpa_commit();
        if (++bf == 4) bf = 0;
    }

    float inv0 = 1.0f / l0, inv1 = 1.0f / l1;
    #pragma unroll
    for (int nt = 0; nt < 8; nt++) {
        int col = h*64 + nt*8 + qc*2;
        if (v0) *(__half2*)&g_oh[((long)b*NTOK + r0)*DIM + col] =
            __floats2half2_rn(oacc[nt].x * inv0, oacc[nt].y * inv0);
        if (v1) *(__half2*)&g_oh[((long)b*NTOK + r1)*DIM + col] =
            __floats2half2_rn(oacc[nt].z * inv1, oacc[nt].w * inv1);
    }
    #undef KS
    #undef VS
}

// ---------------- LayerNorm on easy rows (fp16 out) ----------------
__global__ void k_ln(const float* __restrict__ x, const float* __restrict__ g,
                     const float* __restrict__ be) {
    int b = blockIdx.y, m = blockIdx.x;
    if (m >= g_cntZ[b]) return;
    int tok = g_zidx[b*NTOK + m];
    const float* row = x + ((long)b*NTOK + tok)*DIM;
    int tid = threadIdx.x;
    float v[3];
    float s = 0.0f, s2 = 0.0f;
    #pragma unroll
    for (int i = 0; i < 3; i++) {
        v[i] = row[tid + i*256];
        s += v[i]; s2 += v[i]*v[i];
    }
    __shared__ float r0[256], r1[256];
    r0[tid] = s; r1[tid] = s2;
    __syncthreads();
    for (int off = 128; off; off >>= 1) {
        if (tid < off) { r0[tid] += r0[tid+off]; r1[tid] += r1[tid+off]; }
        __syncthreads();
    }
    float mu  = r0[0] * (1.0f/DIM);
    float var = r1[0] * (1.0f/DIM) - mu*mu;
    float rs  = rsqrtf(var + 1e-5f);
    __half* outp = g_hln + ((long)b*NTOK + m)*DIM;
    #pragma unroll
    for (int i = 0; i < 3; i++) {
        int c = tid + i*256;
        outp[c] = __float2half_rn((v[i] - mu) * rs * g[c] + be[c]);
    }
}

// ---------------- 2-stage masked mean pool + fused ECA ----------------
__global__ void k_pool1() {
    int b = blockIdx.z, part = blockIdx.y;
    int c = blockIdx.x * 256 + threadIdx.x;
    int cz = g_cntZ[b];
    int chunk = (cz + 15) / 16;
    int mlo = part * chunk, mhi = min(mlo + chunk, cz);
    float s = 0.0f;
    for (int m = mlo; m < mhi; m++) s += g_h2[((long)b*NTOK + m)*DIM + c];
    g_poolp[(b*16 + part)*DIM + c] = s;
}

__global__ void k_pool2(const float* __restrict__ w) {
    int b = blockIdx.x, c = threadIdx.x;
    __shared__ float pooled[DIM];
    float s = 0.0f;
    #pragma unroll
    for (int p = 0; p < 16; p++) s += g_poolp[(b*16 + p)*DIM + c];
    pooled[c] = s / fmaxf((float)g_cntZ[b], 1.0f);
    __syncthreads();
    float g = 0.0f;
    #pragma unroll
    for (int tt = 0; tt < 5; tt++) {
        int cc = c + tt - 2;
        if (cc >= 0 && cc < DIM) g += w[tt] * pooled[cc];
    }
    g_sig[b*DIM + c] = 1.0f / (1.0f + __expf(-g));
}

// ---------------- LTRM scatter ----------------
__global__ void k_ltrm(const float* __restrict__ x, float* __restrict__ out) {
    int b = blockIdx.y, m = blockIdx.x;
    if (m >= g_cntZ[b]) return;
    int tok = g_zidx[b*NTOK + m];
    long ro = ((long)b*NTOK + tok)*DIM;
    long ri = ((long)b*NTOK + m)*DIM;
    for (int c = threadIdx.x; c < DIM; c += 256)
        out[ro + c] = x[ro + c] + g_h2[ri + c] * g_sig[b*DIM + c];
}

// ---------------- launch ----------------
extern "C" void kernel_launch(void* const* d_in, const int* in_sizes, int n_in,
                              void* d_out, int out_size) {
    const float* x      = (const float*)d_in[0];
    const float* hint   = (const float*)d_in[1];
    const float* qkv_w  = (const float*)d_in[2];
    const float* qkv_b  = (const float*)d_in[3];
    const float* proj_w = (const float*)d_in[4];
    const float* proj_b = (const float*)d_in[5];
    const float* ln_g   = (const float*)d_in[6];
    const float* ln_b   = (const float*)d_in[7];
    const float* fc1_w  = (const float*)d_in[8];
    const float* fc1_b  = (const float*)d_in[9];
    const float* fc2_w  = (const float*)d_in[10];
    const float* fc2_b  = (const float*)d_in[11];
    const float* eca_w  = (const float*)d_in[12];
    float* out = (float*)d_out;

    __half *d_xh, *d_wqkv, *d_wproj, *d_wfc1, *d_wfc2, *d_oh, *d_hln, *d_h1;
    cudaGetSymbolAddress((void**)&d_xh,   g_xh);
    cudaGetSymbolAddress((void**)&d_wqkv, g_wqkv);
    cudaGetSymbolAddress((void**)&d_wproj,g_wproj);
    cudaGetSymbolAddress((void**)&d_wfc1, g_wfc1);
    cudaGetSymbolAddress((void**)&d_wfc2, g_wfc2);
    cudaGetSymbolAddress((void**)&d_oh,  g_oh);
    cudaGetSymbolAddress((void**)&d_hln, g_hln);
    cudaGetSymbolAddress((void**)&d_h1,  g_h1);

    static bool attr_done = false;
    if (!attr_done) {
        cudaFuncSetAttribute(k_gemm<0>, cudaFuncAttributeMaxDynamicSharedMemorySize, GEMM_SMEM);
        cudaFuncSetAttribute(k_gemm<1>, cudaFuncAttributeMaxDynamicSharedMemorySize, GEMM_SMEM);
        cudaFuncSetAttribute(k_gemm<2>, cudaFuncAttributeMaxDynamicSharedMemorySize, GEMM_SMEM);
        cudaFuncSetAttribute(k_gemm<3>, cudaFuncAttributeMaxDynamicSharedMemorySize, GEMM_SMEM);
        cudaFuncSetAttribute(k_attn,    cudaFuncAttributeMaxDynamicSharedMemorySize, ATTN_SMEM);
        attr_done = true;
    }

    cudaStream_t s2;
    cudaStreamCreateWithFlags(&s2, cudaStreamNonBlocking);
    cudaEvent_t e0, eCvt, eCompact, eEasy;
    cudaEventCreateWithFlags(&e0,       cudaEventDisableTiming);
    cudaEventCreateWithFlags(&eCvt,     cudaEventDisableTiming);
    cudaEventCreateWithFlags(&eCompact, cudaEventDisableTiming);
    cudaEventCreateWithFlags(&eEasy,    cudaEventDisableTiming);

    cudaEventRecord(e0, 0);
    cudaStreamWaitEvent(s2, e0, 0);
    k_cvtall<<<5376, 256, 0, s2>>>(x, qkv_w, proj_w, fc1_w, fc2_w);
    cudaEventRecord(eCvt, s2);

    k_edge   <<<BB*NTOK/8, 256>>>(hint);
    k_compact<<<BB, 1024>>>();
    cudaEventRecord(eCompact, 0);

    // edge path on stream0
    cudaStreamWaitEvent(0, eCvt, 0);
    k_gemm<0><<<dim3(3*DIM/128, NTOK/128, BB), 256, GEMM_SMEM>>>(x, d_xh, d_wqkv, qkv_b, out);
    k_attn   <<<dim3(NTOK/128, HEADS, BB), 256, ATTN_SMEM>>>();
    k_gemm<1><<<dim3(DIM/128, NTOK/128, BB), 256, GEMM_SMEM>>>(x, d_oh, d_wproj, proj_b, out);

    // easy path on s2
    cudaStreamWaitEvent(s2, eCompact, 0);
    k_ln     <<<dim3(NTOK, BB), 256, 0, s2>>>(x, ln_g, ln_b);
    k_gemm<2><<<dim3(HID/128, NTOK/128, BB), 256, GEMM_SMEM, s2>>>(x, d_hln, d_wfc1, fc1_b, out);
    k_gemm<3><<<dim3(DIM/128, NTOK/128, BB), 256, GEMM_SMEM, s2>>>(x, d_h1, d_wfc2, fc2_b, out);
    k_pool1  <<<dim3(DIM/256, 16, BB), 256, 0, s2>>>();
    k_pool2  <<<BB, DIM, 0, s2>>>(eca_w);
    k_ltrm   <<<dim3(NTOK, BB), 256, 0, s2>>>(x, out);
    cudaEventRecord(eEasy, s2);

    cudaStreamWaitEvent(0, eEasy, 0);

    cudaEventDestroy(e0);
    cudaEventDestroy(eCvt);
    cudaEventDestroy(eCompact);
    cudaEventDestroy(eEasy);
    cudaStreamDestroy(s2);
}

// round 12
// speedup vs baseline: 1.0010x; 1.0010x over previous
#include <cuda_runtime.h>
#include <cuda_fp16.h>
#include <math.h>
#include <cstdint>

#define BB     2
#define NTOK   4096
#define DIM    768
#define HEADS  12
#define HD     64
#define HID    1536
#define HINTR  1024

// ---------------- device scratch ----------------
__device__ int    g_edge[BB*NTOK];
__device__ int    g_cntE[BB];
__device__ int    g_cntZ[BB];
__device__ int    g_eidx[BB*NTOK];
__device__ int    g_zidx[BB*NTOK];
__device__ __half g_xh [(size_t)BB*NTOK*DIM];
__device__ __half g_wqkv[(size_t)DIM*3*DIM];
__device__ __half g_wproj[(size_t)DIM*DIM];
__device__ __half g_wfc1[(size_t)DIM*HID];
__device__ __half g_wfc2[(size_t)HID*DIM];
__device__ __half g_qh [(size_t)BB*HEADS*NTOK*HD];
__device__ __half g_kh [(size_t)BB*HEADS*NTOK*HD];
__device__ __half g_vh [(size_t)BB*HEADS*NTOK*HD];
__device__ __half g_oh [(size_t)BB*NTOK*DIM];
__device__ __half g_hln[(size_t)BB*NTOK*DIM];
__device__ __half g_h1 [(size_t)BB*NTOK*HID];
__device__ float  g_h2 [(size_t)BB*NTOK*DIM];
__device__ float  g_poolp[BB*16*DIM];
__device__ float  g_sig [BB*DIM];

// ---------------- asm helpers ----------------
__device__ __forceinline__ void mma16(float4& d, const unsigned* a, unsigned b0, unsigned b1) {
    asm volatile(
        "mma.sync.aligned.m16n8k16.row.col.f32.f16.f16.f32 "
        "{%0,%1,%2,%3}, {%4,%5,%6,%7}, {%8,%9}, {%0,%1,%2,%3};\n"
        : "+f"(d.x), "+f"(d.y), "+f"(d.z), "+f"(d.w)
        : "r"(a[0]), "r"(a[1]), "r"(a[2]), "r"(a[3]), "r"(b0), "r"(b1));
}
__device__ __forceinline__ void ldsm4(unsigned* r, const void* p) {
    unsigned a = (unsigned)__cvta_generic_to_shared(p);
    asm volatile("ldmatrix.sync.aligned.m8n8.x4.shared.b16 {%0,%1,%2,%3}, [%4];\n"
        : "=r"(r[0]), "=r"(r[1]), "=r"(r[2]), "=r"(r[3]) : "r"(a));
}
__device__ __forceinline__ void ldsm4t(unsigned* r, const void* p) {
    unsigned a = (unsigned)__cvta_generic_to_shared(p);
    asm volatile("ldmatrix.sync.aligned.m8n8.x4.trans.shared.b16 {%0,%1,%2,%3}, [%4];\n"
        : "=r"(r[0]), "=r"(r[1]), "=r"(r[2]), "=r"(r[3]) : "r"(a));
}
__device__ __forceinline__ void cpa16(void* smem, const void* gmem) {
    unsigned s = (unsigned)__cvta_generic_to_shared(smem);
    asm volatile("cp.async.cg.shared.global [%0], [%1], 16;\n" :: "r"(s), "l"(gmem));
}
__device__ __forceinline__ void cpa16z(void* smem, const void* gmem, bool pred) {
    unsigned s = (unsigned)__cvta_generic_to_shared(smem);
    int sz = pred ? 16 : 0;
    asm volatile("cp.async.cg.shared.global [%0], [%1], 16, %2;\n" :: "r"(s), "l"(gmem), "r"(sz));
}
__device__ __forceinline__ void cpa_commit() { asm volatile("cp.async.commit_group;\n"); }
__device__ __forceinline__ void cpa_wait2()  { asm volatile("cp.async.wait_group 2;\n"); }
__device__ __forceinline__ unsigned h2u(__half2 h) { return *(unsigned*)&h; }
__device__ __forceinline__ float ex2(float x) {
    float y; asm("ex2.approx.ftz.f32 %0, %1;" : "=f"(y) : "f"(x)); return y;
}

// ---------------- merged fp32 -> fp16 conversion ----------------
__global__ void k_cvtall(const float* __restrict__ x,  const float* __restrict__ w0,
                         const float* __restrict__ w1, const float* __restrict__ w2,
                         const float* __restrict__ w3) {
    int bx = blockIdx.x;
    const float* src; __half* dst; long base;
    if (bx < 3072)      { src = x;  dst = g_xh;    base = (long)bx * 2048; }
    else if (bx < 3936) { src = w0; dst = g_wqkv;  base = (long)(bx - 3072) * 2048; }
    else if (bx < 4224) { src = w1; dst = g_wproj; base = (long)(bx - 3936) * 2048; }
    else if (bx < 4800) { src = w2; dst = g_wfc1;  base = (long)(bx - 4224) * 2048; }
    else                { src = w3; dst = g_wfc2;  base = (long)(bx - 4800) * 2048; }
    long i = base + threadIdx.x * 8;
    float4 f0 = *(const float4*)(src + i);
    float4 f1 = *(const float4*)(src + i + 4);
    __half2 h[4] = { __floats2half2_rn(f0.x, f0.y), __floats2half2_rn(f0.z, f0.w),
                     __floats2half2_rn(f1.x, f1.y), __floats2half2_rn(f1.z, f1.w) };
    *(uint4*)(dst + i) = *(uint4*)h;
}

// ---------------- edge mask ----------------
__global__ void k_edge(const float* __restrict__ hint) {
    int warp = threadIdx.x >> 5, lane = threadIdx.x & 31;
    int token = blockIdx.x * 8 + warp;
    int b = token / NTOK, t = token % NTOK;
    int ty = t >> 6, tx = t & 63;
    const float* base = hint + (size_t)b*HINTR*HINTR + (size_t)(ty*16)*HINTR + tx*16;
    int r = lane >> 1, half = lane & 1;
    const float4* p = (const float4*)(base + (size_t)r*HINTR + half*8);
    float4 a = p[0], c = p[1];
    float s = a.x+a.y+a.z+a.w + c.x+c.y+c.z+c.w;
    #pragma unroll
    for (int off = 16; off; off >>= 1) s += __shfl_down_sync(0xffffffffu, s, off);
    if (lane == 0) {
        float mean = s * (1.0f/256.0f);
        g_edge[token] = (mean > 0.02f && mean < 0.98f) ? 1 : 0;
    }
}

// ---------------- compaction with folded fallback ----------------
__global__ void k_compact() {
    int b = blockIdx.x, tid = threadIdx.x;
    int t0 = tid * 4;
    int f[4]; int e = 0;
    #pragma unroll
    for (int i = 0; i < 4; i++) { f[i] = g_edge[b*NTOK + t0 + i]; e += f[i]; }
    int lane = tid & 31, wid = tid >> 5;
    int v = e;
    #pragma unroll
    for (int off = 1; off < 32; off <<= 1) {
        int n = __shfl_up_sync(0xffffffffu, v, off);
        if (lane >= off) v += n;
    }
    __shared__ int wsum[32];
    if (lane == 31) wsum[wid] = v;
    __syncthreads();
    if (wid == 0) {
        int wv = wsum[lane];
        #pragma unroll
        for (int off = 1; off < 32; off <<= 1) {
            int n = __shfl_up_sync(0xffffffffu, wv, off);
            if (lane >= off) wv += n;
        }
        wsum[lane] = wv;
    }
    __syncthreads();
    int tot = wsum[31];
    if (tot < 64) {
        #pragma unroll
        for (int i = 0; i < 4; i++) g_eidx[b*NTOK + t0 + i] = t0 + i;
        if (tid == 1023) { g_cntE[b] = NTOK; g_cntZ[b] = 0; }
        return;
    }
    int excl = v - e + (wid ? wsum[wid-1] : 0);
    int eoff = excl, zoff = t0 - excl;
    #pragma unroll
    for (int i = 0; i < 4; i++) {
        if (f[i]) g_eidx[b*NTOK + eoff++] = t0 + i;
        else      g_zidx[b*NTOK + zoff++] = t0 + i;
    }
    if (tid == 1023) { g_cntE[b] = tot; g_cntZ[b] = NTOK - tot; }
}

// ---------------- fp16 MMA GEMM: 4-stage ring, wait_group 2 ----------------
__device__ __forceinline__ float gelu_exact(float x) {
    return 0.5f * x * (1.0f + erff(x * 0.70710678118654752f));
}

#define GEMM_SMEM (4*(128*40 + 32*136)*2)   // 75776 B

template<int EPI>
__global__ void __launch_bounds__(256)
k_gemm(const float* __restrict__ xfull, const __half* __restrict__ A,
       const __half* __restrict__ W, const float* __restrict__ bias,
       float* __restrict__ dout)
{
    constexpr int K = (EPI == 3) ? HID : DIM;
    constexpr int N = (EPI == 0) ? 3*DIM : (EPI == 2 ? HID : DIM);
    constexpr int NT = K / 32;
    const int* cntp = (EPI >= 2) ? g_cntZ : g_cntE;

    int b = blockIdx.z;
    int M = cntp[b];
    int m0 = blockIdx.y * 128;
    if (m0 >= M) return;
    int n0 = blockIdx.x * 128;
    const __half* Ab = A + (long)b * NTOK * K;

    extern __shared__ __align__(16) __half smg[];
    __half* As_ = smg;                   // 4 bufs x 128 x 40
    __half* Bs_ = smg + 4*128*40;        // 4 bufs x 32 x 136
    #define AS(bf,m,k)  As_[(bf)*5120 + (m)*40 + (k)]
    #define BS(bf,kr,n) Bs_[(bf)*4352 + (kr)*136 + (n)]

    int tid = threadIdx.x;
    int w = tid >> 5, lane = tid & 31;
    int wm = (w >> 2) * 64, wn = (w & 3) * 32;
    int qr = lane >> 2, qc = lane & 3;

    int  mA[2], cA[2], krB[2], cB[2];
    long arow[2];
    #pragma unroll
    for (int t = 0; t < 2; t++) {
        int task = tid + 256*t;
        mA[t] = task >> 2; cA[t] = (task & 3) * 8;
        int gm = m0 + mA[t];
        arow[t] = (gm < M) ? (long)((EPI == 0) ? g_eidx[b*NTOK + gm] : gm) * K : -1;
        krB[t] = task >> 4; cB[t] = (task & 15) * 8;
    }

    auto issue = [&](int k0, int bf) {
        #pragma unroll
        for (int t = 0; t < 2; t++) {
            const __half* asrc = (arow[t] >= 0) ? (Ab + arow[t] + k0 + cA[t]) : Ab;
            cpa16z(&AS(bf, mA[t], cA[t]), asrc, arow[t] >= 0);
            cpa16(&BS(bf, krB[t], cB[t]), W + (long)(k0 + krB[t])*N + n0 + cB[t]);
        }
    };

    float4 acc[4][4];
    #pragma unroll
    for (int i = 0; i < 4; i++)
        #pragma unroll
        for (int j = 0; j < 4; j++) acc[i][j] = make_float4(0,0,0,0);

    issue(0, 0);  cpa_commit();
    issue(32, 1); cpa_commit();
    issue(64, 2); cpa_commit();

    int bf = 0;
    #pragma unroll 1
    for (int it = 0; it < NT; it++) {
        cpa_wait2();
        __syncthreads();
        unsigned bfr[4][4];
        #pragma unroll
        for (int ni = 0; ni < 4; ni++)
            ldsm4t(bfr[ni], &BS(bf, lane, wn + ni*8));
        #pragma unroll
        for (int ks = 0; ks < 2; ks++) {
            unsigned afr[4][4];
            #pragma unroll
            for (int mi = 0; mi < 4; mi++)
                ldsm4(afr[mi], &AS(bf, wm + mi*16 + (lane & 15), ks*16 + (lane >> 4)*8));
            #pragma unroll
            for (int ni = 0; ni < 4; ni++)
                #pragma unroll
                for (int mi = 0; mi < 4; mi++)
                    mma16(acc[mi][ni], afr[mi], bfr[ni][ks*2], bfr[ni][ks*2+1]);
        }
        if (it + 3 < NT) {
            int nb = bf + 3; if (nb >= 4) nb -= 4;
            issue((it + 3) * 32, nb);
        }
        cpa_commit();
        if (++bf == 4) bf = 0;
    }

    #pragma unroll
    for (int mi = 0; mi < 4; mi++) {
        int rowA = m0 + wm + mi*16 + qr;
        int rowB = rowA + 8;
        #pragma unroll
        for (int ni = 0; ni < 4; ni++) {
            int col = n0 + wn + ni*8 + qc*2;
            float b0v = bias[col], b1v = bias[col+1];
            float vx = acc[mi][ni].x + b0v, vy = acc[mi][ni].y + b1v;
            float vz = acc[mi][ni].z + b0v, vw = acc[mi][ni].w + b1v;
            if (EPI == 0) {
                int part = col / DIM, cc = col - part*DIM;
                __half* dst = (part == 0) ? g_qh : (part == 1) ? g_kh : g_vh;
                int h = cc >> 6, d = cc & 63;
                long hb = ((long)b*HEADS + h)*NTOK;
                if (rowA < M) *(__half2*)&dst[(hb + rowA)*HD + d] = __floats2half2_rn(vx, vy);
                if (rowB < M) *(__half2*)&dst[(hb + rowB)*HD + d] = __floats2half2_rn(vz, vw);
            } else if (EPI == 1) {
                if (rowA < M) {
                    long o = ((long)b*NTOK + g_eidx[b*NTOK + rowA])*DIM + col;
                    *(float2*)&dout[o] = make_float2(vx + xfull[o], vy + xfull[o+1]);
                }
                if (rowB < M) {
                    long o = ((long)b*NTOK + g_eidx[b*NTOK + rowB])*DIM + col;
                    *(float2*)&dout[o] = make_float2(vz + xfull[o], vw + xfull[o+1]);
                }
            } else if (EPI == 2) {
                if (rowA < M) *(__half2*)&g_h1[((long)b*NTOK + rowA)*HID + col] =
                    __floats2half2_rn(gelu_exact(gelu_exact(vx)), gelu_exact(gelu_exact(vy)));
                if (rowB < M) *(__half2*)&g_h1[((long)b*NTOK + rowB)*HID + col] =
                    __floats2half2_rn(gelu_exact(gelu_exact(vz)), gelu_exact(gelu_exact(vw)));
            } else {
                if (rowA < M) *(float2*)&g_h2[((long)b*NTOK + rowA)*DIM + col] = make_float2(vx, vy);
                if (rowB < M) *(float2*)&g_h2[((long)b*NTOK + rowB)*DIM + col] = make_float2(vz, vw);
            }
        }
    }
    #undef AS
    #undef BS
}

// ---------------- fp16 flash attention: KT=64, 4-stage ring, wait_group 2 ----------------
#define KT 64
#define ATTN_SMEM (4*KT*72*2*2)   // 73728 B

__global__ void __launch_bounds__(256) k_attn() {
    int b = blockIdx.z, h = blockIdx.y;
    int M = g_cntE[b];
    int m0 = blockIdx.x * 128;
    if (m0 >= M) return;
    int tid = threadIdx.x, w = tid >> 5, lane = tid & 31;
    int qr = lane >> 2, qc = lane & 3;
    long base = ((long)b*HEADS + h)*NTOK*HD;

    extern __shared__ __align__(16) __half sma[];
    __half* Ks_ = sma;              // 4 x 64 x 72
    __half* Vs_ = sma + 4*KT*72;
    #define KS(bf,r,c) Ks_[(bf)*(KT*72) + (r)*72 + (c)]
    #define VS(bf,r,c) Vs_[(bf)*(KT*72) + (r)*72 + (c)]

    int r0 = m0 + w*16 + qr, r1 = r0 + 8;
    bool v0 = r0 < M, v1 = r1 < M;
    const __half* q0p = g_qh + base + (long)r0*HD;
    const __half* q1p = g_qh + base + (long)r1*HD;
    unsigned qf[4][4];
    #pragma unroll
    for (int ks = 0; ks < 4; ks++) {
        int c = ks*16 + qc*2;
        qf[ks][0] = v0 ? *(const unsigned*)&q0p[c]   : 0u;
        qf[ks][1] = v1 ? *(const unsigned*)&q1p[c]   : 0u;
        qf[ks][2] = v0 ? *(const unsigned*)&q0p[c+8] : 0u;
        qf[ks][3] = v1 ? *(const unsigned*)&q1p[c+8] : 0u;
    }

    auto issue = [&](int kb, int bf) {
        #pragma unroll
        for (int t = 0; t < 4; t++) {
            int task = tid + 256*t;            // 0..1023
            int mat  = task >> 9;
            int t2   = task & 511;
            int row  = t2 >> 3;
            int c8   = (t2 & 7) * 8;
            bool ok = (kb + row) < M;
            const __half* src = (mat ? g_vh : g_kh) + base + (long)(kb + (ok ? row : 0))*HD + c8;
            if (mat) cpa16z(&VS(bf, row, c8), src, ok);
            else     cpa16z(&KS(bf, row, c8), src, ok);
        }
    };

    float4 oacc[8];
    #pragma unroll
    for (int i = 0; i < 8; i++) oacc[i] = make_float4(0,0,0,0);
    float mx0 = -1e30f, mx1 = -1e30f, l0 = 0.0f, l1 = 0.0f;
    const float SC = 0.125f * 1.44269504088896340736f;

    int ntiles = (M + KT - 1) / KT;
    issue(0, 0); cpa_commit();
    if (ntiles > 1) issue(KT, 1);
    cpa_commit();
    if (ntiles > 2) issue(2*KT, 2);
    cpa_commit();

    int bf = 0;
    #pragma unroll 1
    for (int kt = 0; kt < ntiles; kt++) {
        int kb = kt * KT;
        cpa_wait2();
        __syncthreads();

        float4 s[8];
        #pragma unroll
        for (int nt = 0; nt < 8; nt++) s[nt] = make_float4(0,0,0,0);
        #pragma unroll
        for (int dh = 0; dh < 2; dh++) {
            #pragma unroll
            for (int nt = 0; nt < 8; nt++) {
                unsigned kf[4];
                ldsm4(kf, &KS(bf, nt*8 + (lane & 7), (lane >> 3)*8 + dh*32));
                mma16(s[nt], qf[dh*2],     kf[0], kf[1]);
                mma16(s[nt], qf[dh*2 + 1], kf[2], kf[3]);
            }
        }
        float t0 = -1e30f, t1 = -1e30f;
        #pragma unroll
        for (int nt = 0; nt < 8; nt++) {
            s[nt].x *= SC; s[nt].y *= SC; s[nt].z *= SC; s[nt].w *= SC;
            int c0 = kb + nt*8 + qc*2;
            if (c0     >= M) { s[nt].x = -1e30f; s[nt].z = -1e30f; }
            if (c0 + 1 >= M) { s[nt].y = -1e30f; s[nt].w = -1e30f; }
            t0 = fmaxf(t0, fmaxf(s[nt].x, s[nt].y));
            t1 = fmaxf(t1, fmaxf(s[nt].z, s[nt].w));
        }
        t0 = fmaxf(t0, __shfl_xor_sync(0xffffffffu, t0, 1));
        t0 = fmaxf(t0, __shfl_xor_sync(0xffffffffu, t0, 2));
        t1 = fmaxf(t1, __shfl_xor_sync(0xffffffffu, t1, 1));
        t1 = fmaxf(t1, __shfl_xor_sync(0xffffffffu, t1, 2));
        float nm0 = fmaxf(mx0, t0), nm1 = fmaxf(mx1, t1);
        bool nochg = (nm0 == mx0) && (nm1 == mx1);
        if (!__all_sync(0xffffffffu, nochg)) {
            float cr0 = ex2(mx0 - nm0), cr1 = ex2(mx1 - nm1);
            l0 *= cr0; l1 *= cr1;
            #pragma unroll
            for (int i = 0; i < 8; i++) {
                oacc[i].x *= cr0; oacc[i].y *= cr0;
                oacc[i].z *= cr1; oacc[i].w *= cr1;
            }
        }
        mx0 = nm0; mx1 = nm1;

        float ps0 = 0.0f, ps1 = 0.0f;
        unsigned pa[4][4];
        #pragma unroll
        for (int nt = 0; nt < 8; nt++) {
            float px = ex2(s[nt].x - mx0), py = ex2(s[nt].y - mx0);
            float pz = ex2(s[nt].z - mx1), pw = ex2(s[nt].w - mx1);
            ps0 += px + py; ps1 += pz + pw;
            int ks = nt >> 1, hi = (nt & 1) * 2;
            pa[ks][hi]     = h2u(__floats2half2_rn(px, py));
            pa[ks][hi + 1] = h2u(__floats2half2_rn(pz, pw));
        }
        ps0 += __shfl_xor_sync(0xffffffffu, ps0, 1);
        ps0 += __shfl_xor_sync(0xffffffffu, ps0, 2);
        ps1 += __shfl_xor_sync(0xffffffffu, ps1, 1);
        ps1 += __shfl_xor_sync(0xffffffffu, ps1, 2);
        l0 += ps0; l1 += ps1;

        #pragma unroll
        for (int ks = 0; ks < 4; ks++) {
            unsigned vf[4][4];
            #pragma unroll
            for (int dp = 0; dp < 4; dp++)
                ldsm4t(vf[dp], &VS(bf, 16*ks + ((lane >> 3) & 1)*8 + (lane & 7),
                                   dp*16 + (lane >> 4)*8));
            #pragma unroll
            for (int nt = 0; nt < 8; nt++)
                mma16(oacc[nt], pa[ks], vf[nt >> 1][(nt & 1)*2], vf[nt >> 1][(nt & 1)*2 + 1]);
        }

        if (kt + 3 < ntiles) {
            int nb = bf + 3; if (nb >= 4) nb -= 4;
            issue(kb + 3*KT, nb);
        }
        cpa_commit();
        if (++bf == 4) bf = 0;
    }

    float inv0 = 1.0f / l0, inv1 = 1.0f / l1;
    #pragma unroll
    for (int nt = 0; nt < 8; nt++) {
        int col = h*64 + nt*8 + qc*2;
        if (v0) *(__half2*)&g_oh[((long)b*NTOK + r0)*DIM + col] =
            __floats2half2_rn(oacc[nt].x * inv0, oacc[nt].y * inv0);
        if (v1) *(__half2*)&g_oh[((long)b*NTOK + r1)*DIM + col] =
            __floats2half2_rn(oacc[nt].z * inv1, oacc[nt].w * inv1);
    }
    #undef KS
    #undef VS
}

// ---------------- LayerNorm on easy rows (fp16 out) ----------------
__global__ void k_ln(const float* __restrict__ x, const float* __restrict__ g,
                     const float* __restrict__ be) {
    int b = blockIdx.y, m = blockIdx.x;
    if (m >= g_cntZ[b]) return;
    int tok = g_zidx[b*NTOK + m];
    const float* row = x + ((long)b*NTOK + tok)*DIM;
    int tid = threadIdx.x;
    float v[3];
    float s = 0.0f, s2 = 0.0f;
    #pragma unroll
    for (int i = 0; i < 3; i++) {
        v[i] = row[tid + i*256];
        s += v[i]; s2 += v[i]*v[i];
    }
    __shared__ float r0[256], r1[256];
    r0[tid] = s; r1[tid] = s2;
    __syncthreads();
    for (int off = 128; off; off >>= 1) {
        if (tid < off) { r0[tid] += r0[tid+off]; r1[tid] += r1[tid+off]; }
        __syncthreads();
    }
    float mu  = r0[0] * (1.0f/DIM);
    float var = r1[0] * (1.0f/DIM) - mu*mu;
    float rs  = rsqrtf(var + 1e-5f);
    __half* outp = g_hln + ((long)b*NTOK + m)*DIM;
    #pragma unroll
    for (int i = 0; i < 3; i++) {
        int c = tid + i*256;
        outp[c] = __float2half_rn((v[i] - mu) * rs * g[c] + be[c]);
    }
}

// ---------------- 2-stage masked mean pool + fused ECA ----------------
__global__ void k_pool1() {
    int b = blockIdx.z, part = blockIdx.y;
    int c = blockIdx.x * 256 + threadIdx.x;
    int cz = g_cntZ[b];
    int chunk = (cz + 15) / 16;
    int mlo = part * chunk, mhi = min(mlo + chunk, cz);
    float s = 0.0f;
    for (int m = mlo; m < mhi; m++) s += g_h2[((long)b*NTOK + m)*DIM + c];
    g_poolp[(b*16 + part)*DIM + c] = s;
}

__global__ void k_pool2(const float* __restrict__ w) {
    int b = blockIdx.x, c = threadIdx.x;
    __shared__ float pooled[DIM];
    float s = 0.0f;
    #pragma unroll
    for (int p = 0; p < 16; p++) s += g_poolp[(b*16 + p)*DIM + c];
    pooled[c] = s / fmaxf((float)g_cntZ[b], 1.0f);
    __syncthreads();
    float g = 0.0f;
    #pragma unroll
    for (int tt = 0; tt < 5; tt++) {
        int cc = c + tt - 2;
        if (cc >= 0 && cc < DIM) g += w[tt] * pooled[cc];
    }
    g_sig[b*DIM + c] = 1.0f / (1.0f + __expf(-g));
}

// ---------------- LTRM scatter ----------------
__global__ void k_ltrm(const float* __restrict__ x, float* __restrict__ out) {
    int b = blockIdx.y, m = blockIdx.x;
    if (m >= g_cntZ[b]) return;
    int tok = g_zidx[b*NTOK + m];
    long ro = ((long)b*NTOK + tok)*DIM;
    long ri = ((long)b*NTOK + m)*DIM;
    for (int c = threadIdx.x; c < DIM; c += 256)
        out[ro + c] = x[ro + c] + g_h2[ri + c] * g_sig[b*DIM + c];
}

// ---------------- launch ----------------
extern "C" void kernel_launch(void* const* d_in, const int* in_sizes, int n_in,
                              void* d_out, int out_size) {
    const float* x      = (const float*)d_in[0];
    const float* hint   = (const float*)d_in[1];
    const float* qkv_w  = (const float*)d_in[2];
    const float* qkv_b  = (const float*)d_in[3];
    const float* proj_w = (const float*)d_in[4];
    const float* proj_b = (const float*)d_in[5];
    const float* ln_g   = (const float*)d_in[6];
    const float* ln_b   = (const float*)d_in[7];
    const float* fc1_w  = (const float*)d_in[8];
    const float* fc1_b  = (const float*)d_in[9];
    const float* fc2_w  = (const float*)d_in[10];
    const float* fc2_b  = (const float*)d_in[11];
    const float* eca_w  = (const float*)d_in[12];
    float* out = (float*)d_out;

    __half *d_xh, *d_wqkv, *d_wproj, *d_wfc1, *d_wfc2, *d_oh, *d_hln, *d_h1;
    cudaGetSymbolAddress((void**)&d_xh,   g_xh);
    cudaGetSymbolAddress((void**)&d_wqkv, g_wqkv);
    cudaGetSymbolAddress((void**)&d_wproj,g_wproj);
    cudaGetSymbolAddress((void**)&d_wfc1, g_wfc1);
    cudaGetSymbolAddress((void**)&d_wfc2, g_wfc2);
    cudaGetSymbolAddress((void**)&d_oh,  g_oh);
    cudaGetSymbolAddress((void**)&d_hln, g_hln);
    cudaGetSymbolAddress((void**)&d_h1,  g_h1);

    static bool attr_done = false;
    if (!attr_done) {
        cudaFuncSetAttribute(k_gemm<0>, cudaFuncAttributeMaxDynamicSharedMemorySize, GEMM_SMEM);
        cudaFuncSetAttribute(k_gemm<1>, cudaFuncAttributeMaxDynamicSharedMemorySize, GEMM_SMEM);
        cudaFuncSetAttribute(k_gemm<2>, cudaFuncAttributeMaxDynamicSharedMemorySize, GEMM_SMEM);
        cudaFuncSetAttribute(k_gemm<3>, cudaFuncAttributeMaxDynamicSharedMemorySize, GEMM_SMEM);
        cudaFuncSetAttribute(k_attn,    cudaFuncAttributeMaxDynamicSharedMemorySize, ATTN_SMEM);
        attr_done = true;
    }

    cudaStream_t s2;
    cudaStreamCreateWithFlags(&s2, cudaStreamNonBlocking);
    cudaEvent_t e0, eCvt, eCompact, eEasy;
    cudaEventCreateWithFlags(&e0,       cudaEventDisableTiming);
    cudaEventCreateWithFlags(&eCvt,     cudaEventDisableTiming);
    cudaEventCreateWithFlags(&eCompact, cudaEventDisableTiming);
    cudaEventCreateWithFlags(&eEasy,    cudaEventDisableTiming);

    cudaEventRecord(e0, 0);
    cudaStreamWaitEvent(s2, e0, 0);
    k_cvtall<<<5376, 256, 0, s2>>>(x, qkv_w, proj_w, fc1_w, fc2_w);
    cudaEventRecord(eCvt, s2);

    k_edge   <<<BB*NTOK/8, 256>>>(hint);
    k_compact<<<BB, 1024>>>();
    cudaEventRecord(eCompact, 0);

    // edge path on stream0
    cudaStreamWaitEvent(0, eCvt, 0);
    k_gemm<0><<<dim3(3*DIM/128, NTOK/128, BB), 256, GEMM_SMEM>>>(x, d_xh, d_wqkv, qkv_b, out);
    k_attn   <<<dim3(NTOK/128, HEADS, BB), 256, ATTN_SMEM>>>();
    k_gemm<1><<<dim3(DIM/128, NTOK/128, BB), 256, GEMM_SMEM>>>(x, d_oh, d_wproj, proj_b, out);

    // easy path on s2
    cudaStreamWaitEvent(s2, eCompact, 0);
    k_ln     <<<dim3(NTOK, BB), 256, 0, s2>>>(x, ln_g, ln_b);
    k_gemm<2><<<dim3(HID/128, NTOK/128, BB), 256, GEMM_SMEM, s2>>>(x, d_hln, d_wfc1, fc1_b, out);
    k_gemm<3><<<dim3(DIM/128, NTOK/128, BB), 256, GEMM_SMEM, s2>>>(x, d_h1, d_wfc2, fc2_b, out);
    k_pool1  <<<dim3(DIM/256, 16, BB), 256, 0, s2>>>();
    k_pool2  <<<BB, DIM, 0, s2>>>(eca_w);
    k_ltrm   <<<dim3(NTOK, BB), 256, 0, s2>>>(x, out);
    cudaEventRecord(eEasy, s2);

    cudaStreamWaitEvent(0, eEasy, 0);

    cudaEventDestroy(e0);
    cudaEventDestroy(eCvt);
    cudaEventDestroy(eCompact);
    cudaEventDestroy(eEasy);
    cudaStreamDestroy(s2);
}

// round 13
// speedup vs baseline: 1.0015x; 1.0005x over previous
#include <cuda_runtime.h>
#include <cuda_fp16.h>
#include <math.h>
#include <cstdint>

#define BB     2
#define NTOK   4096
#define DIM    768
#define HEADS  12
#define HD     64
#define HID    1536
#define HINTR  1024

// ---------------- device scratch ----------------
__device__ int    g_edge[BB*NTOK];
__device__ int    g_cntE[BB];
__device__ int    g_cntZ[BB];
__device__ int    g_eidx[BB*NTOK];
__device__ int    g_zidx[BB*NTOK];
__device__ __half g_xh [(size_t)BB*NTOK*DIM];
__device__ __half g_wqkv[(size_t)DIM*3*DIM];
__device__ __half g_wproj[(size_t)DIM*DIM];
__device__ __half g_wfc1[(size_t)DIM*HID];
__device__ __half g_wfc2[(size_t)HID*DIM];
__device__ __half g_qh [(size_t)BB*HEADS*NTOK*HD];
__device__ __half g_kh [(size_t)BB*HEADS*NTOK*HD];
__device__ __half g_vh [(size_t)BB*HEADS*NTOK*HD];
__device__ __half g_oh [(size_t)BB*NTOK*DIM];
__device__ __half g_hln[(size_t)BB*NTOK*DIM];
__device__ __half g_h1 [(size_t)BB*NTOK*HID];
__device__ float  g_h2 [(size_t)BB*NTOK*DIM];
__device__ float  g_poolp[BB*16*DIM];
__device__ float  g_sig [BB*DIM];

// ---------------- asm helpers ----------------
__device__ __forceinline__ void mma16(float4& d, const unsigned* a, unsigned b0, unsigned b1) {
    asm volatile(
        "mma.sync.aligned.m16n8k16.row.col.f32.f16.f16.f32 "
        "{%0,%1,%2,%3}, {%4,%5,%6,%7}, {%8,%9}, {%0,%1,%2,%3};\n"
        : "+f"(d.x), "+f"(d.y), "+f"(d.z), "+f"(d.w)
        : "r"(a[0]), "r"(a[1]), "r"(a[2]), "r"(a[3]), "r"(b0), "r"(b1));
}
__device__ __forceinline__ void ldsm4(unsigned* r, const void* p) {
    unsigned a = (unsigned)__cvta_generic_to_shared(p);
    asm volatile("ldmatrix.sync.aligned.m8n8.x4.shared.b16 {%0,%1,%2,%3}, [%4];\n"
        : "=r"(r[0]), "=r"(r[1]), "=r"(r[2]), "=r"(r[3]) : "r"(a));
}
__device__ __forceinline__ void ldsm4t(unsigned* r, const void* p) {
    unsigned a = (unsigned)__cvta_generic_to_shared(p);
    asm volatile("ldmatrix.sync.aligned.m8n8.x4.trans.shared.b16 {%0,%1,%2,%3}, [%4];\n"
        : "=r"(r[0]), "=r"(r[1]), "=r"(r[2]), "=r"(r[3]) : "r"(a));
}
__device__ __forceinline__ void cpa16(void* smem, const void* gmem) {
    unsigned s = (unsigned)__cvta_generic_to_shared(smem);
    asm volatile("cp.async.cg.shared.global [%0], [%1], 16;\n" :: "r"(s), "l"(gmem));
}
__device__ __forceinline__ void cpa16z(void* smem, const void* gmem, bool pred) {
    unsigned s = (unsigned)__cvta_generic_to_shared(smem);
    int sz = pred ? 16 : 0;
    asm volatile("cp.async.cg.shared.global [%0], [%1], 16, %2;\n" :: "r"(s), "l"(gmem), "r"(sz));
}
__device__ __forceinline__ void cpa_commit() { asm volatile("cp.async.commit_group;\n"); }
__device__ __forceinline__ void cpa_wait2()  { asm volatile("cp.async.wait_group 2;\n"); }
__device__ __forceinline__ unsigned h2u(__half2 h) { return *(unsigned*)&h; }
__device__ __forceinline__ float ex2(float x) {
    float y; asm("ex2.approx.ftz.f32 %0, %1;" : "=f"(y) : "f"(x)); return y;
}

// ---------------- merged fp32 -> fp16 conversion ----------------
__global__ void k_cvtall(const float* __restrict__ x,  const float* __restrict__ w0,
                         const float* __restrict__ w1, const float* __restrict__ w2,
                         const float* __restrict__ w3) {
    int bx = blockIdx.x;
    const float* src; __half* dst; long base;
    if (bx < 3072)      { src = x;  dst = g_xh;    base = (long)bx * 2048; }
    else if (bx < 3936) { src = w0; dst = g_wqkv;  base = (long)(bx - 3072) * 2048; }
    else if (bx < 4224) { src = w1; dst = g_wproj; base = (long)(bx - 3936) * 2048; }
    else if (bx < 4800) { src = w2; dst = g_wfc1;  base = (long)(bx - 4224) * 2048; }
    else                { src = w3; dst = g_wfc2;  base = (long)(bx - 4800) * 2048; }
    long i = base + threadIdx.x * 8;
    float4 f0 = *(const float4*)(src + i);
    float4 f1 = *(const float4*)(src + i + 4);
    __half2 h[4] = { __floats2half2_rn(f0.x, f0.y), __floats2half2_rn(f0.z, f0.w),
                     __floats2half2_rn(f1.x, f1.y), __floats2half2_rn(f1.z, f1.w) };
    *(uint4*)(dst + i) = *(uint4*)h;
}

// ---------------- edge mask ----------------
__global__ void k_edge(const float* __restrict__ hint) {
    int warp = threadIdx.x >> 5, lane = threadIdx.x & 31;
    int token = blockIdx.x * 8 + warp;
    int b = token / NTOK, t = token % NTOK;
    int ty = t >> 6, tx = t & 63;
    const float* base = hint + (size_t)b*HINTR*HINTR + (size_t)(ty*16)*HINTR + tx*16;
    int r = lane >> 1, half = lane & 1;
    const float4* p = (const float4*)(base + (size_t)r*HINTR + half*8);
    float4 a = p[0], c = p[1];
    float s = a.x+a.y+a.z+a.w + c.x+c.y+c.z+c.w;
    #pragma unroll
    for (int off = 16; off; off >>= 1) s += __shfl_down_sync(0xffffffffu, s, off);
    if (lane == 0) {
        float mean = s * (1.0f/256.0f);
        g_edge[token] = (mean > 0.02f && mean < 0.98f) ? 1 : 0;
    }
}

// ---------------- compaction with folded fallback ----------------
__global__ void k_compact() {
    int b = blockIdx.x, tid = threadIdx.x;
    int t0 = tid * 4;
    int f[4]; int e = 0;
    #pragma unroll
    for (int i = 0; i < 4; i++) { f[i] = g_edge[b*NTOK + t0 + i]; e += f[i]; }
    int lane = tid & 31, wid = tid >> 5;
    int v = e;
    #pragma unroll
    for (int off = 1; off < 32; off <<= 1) {
        int n = __shfl_up_sync(0xffffffffu, v, off);
        if (lane >= off) v += n;
    }
    __shared__ int wsum[32];
    if (lane == 31) wsum[wid] = v;
    __syncthreads();
    if (wid == 0) {
        int wv = wsum[lane];
        #pragma unroll
        for (int off = 1; off < 32; off <<= 1) {
            int n = __shfl_up_sync(0xffffffffu, wv, off);
            if (lane >= off) wv += n;
        }
        wsum[lane] = wv;
    }
    __syncthreads();
    int tot = wsum[31];
    if (tot < 64) {
        #pragma unroll
        for (int i = 0; i < 4; i++) g_eidx[b*NTOK + t0 + i] = t0 + i;
        if (tid == 1023) { g_cntE[b] = NTOK; g_cntZ[b] = 0; }
        return;
    }
    int excl = v - e + (wid ? wsum[wid-1] : 0);
    int eoff = excl, zoff = t0 - excl;
    #pragma unroll
    for (int i = 0; i < 4; i++) {
        if (f[i]) g_eidx[b*NTOK + eoff++] = t0 + i;
        else      g_zidx[b*NTOK + zoff++] = t0 + i;
    }
    if (tid == 1023) { g_cntE[b] = tot; g_cntZ[b] = NTOK - tot; }
}

// ---------------- fp16 MMA GEMM: 4-stage ring, wait_group 2 ----------------
__device__ __forceinline__ float gelu_exact(float x) {
    return 0.5f * x * (1.0f + erff(x * 0.70710678118654752f));
}

#define GEMM_SMEM (4*(128*40 + 32*136)*2)   // 75776 B

template<int EPI>
__global__ void __launch_bounds__(256)
k_gemm(const float* __restrict__ xfull, const __half* __restrict__ A,
       const __half* __restrict__ W, const float* __restrict__ bias,
       float* __restrict__ dout)
{
    constexpr int K = (EPI == 3) ? HID : DIM;
    constexpr int N = (EPI == 0) ? 3*DIM : (EPI == 2 ? HID : DIM);
    constexpr int NT = K / 32;
    const int* cntp = (EPI >= 2) ? g_cntZ : g_cntE;

    int b = blockIdx.z;
    int M = cntp[b];
    int m0 = blockIdx.y * 128;
    if (m0 >= M) return;
    int n0 = blockIdx.x * 128;
    const __half* Ab = A + (long)b * NTOK * K;

    extern __shared__ __align__(16) __half smg[];
    __half* As_ = smg;                   // 4 bufs x 128 x 40
    __half* Bs_ = smg + 4*128*40;        // 4 bufs x 32 x 136
    #define AS(bf,m,k)  As_[(bf)*5120 + (m)*40 + (k)]
    #define BS(bf,kr,n) Bs_[(bf)*4352 + (kr)*136 + (n)]

    int tid = threadIdx.x;
    int w = tid >> 5, lane = tid & 31;
    int wm = (w >> 2) * 64, wn = (w & 3) * 32;
    int qr = lane >> 2, qc = lane & 3;

    int  mA[2], cA[2], krB[2], cB[2];
    long arow[2];
    #pragma unroll
    for (int t = 0; t < 2; t++) {
        int task = tid + 256*t;
        mA[t] = task >> 2; cA[t] = (task & 3) * 8;
        int gm = m0 + mA[t];
        arow[t] = (gm < M) ? (long)((EPI == 0) ? g_eidx[b*NTOK + gm] : gm) * K : -1;
        krB[t] = task >> 4; cB[t] = (task & 15) * 8;
    }

    auto issue = [&](int k0, int bf) {
        #pragma unroll
        for (int t = 0; t < 2; t++) {
            const __half* asrc = (arow[t] >= 0) ? (Ab + arow[t] + k0 + cA[t]) : Ab;
            cpa16z(&AS(bf, mA[t], cA[t]), asrc, arow[t] >= 0);
            cpa16(&BS(bf, krB[t], cB[t]), W + (long)(k0 + krB[t])*N + n0 + cB[t]);
        }
    };

    float4 acc[4][4];
    #pragma unroll
    for (int i = 0; i < 4; i++)
        #pragma unroll
        for (int j = 0; j < 4; j++) acc[i][j] = make_float4(0,0,0,0);

    issue(0, 0);  cpa_commit();
    issue(32, 1); cpa_commit();
    issue(64, 2); cpa_commit();

    int bf = 0;
    #pragma unroll 1
    for (int it = 0; it < NT; it++) {
        cpa_wait2();
        __syncthreads();
        unsigned bfr[4][4];
        #pragma unroll
        for (int ni = 0; ni < 4; ni++)
            ldsm4t(bfr[ni], &BS(bf, lane, wn + ni*8));
        #pragma unroll
        for (int ks = 0; ks < 2; ks++) {
            unsigned afr[4][4];
            #pragma unroll
            for (int mi = 0; mi < 4; mi++)
                ldsm4(afr[mi], &AS(bf, wm + mi*16 + (lane & 15), ks*16 + (lane >> 4)*8));
            #pragma unroll
            for (int ni = 0; ni < 4; ni++)
                #pragma unroll
                for (int mi = 0; mi < 4; mi++)
                    mma16(acc[mi][ni], afr[mi], bfr[ni][ks*2], bfr[ni][ks*2+1]);
        }
        if (it + 3 < NT) {
            int nb = bf + 3; if (nb >= 4) nb -= 4;
            issue((it + 3) * 32, nb);
        }
        cpa_commit();
        if (++bf == 4) bf = 0;
    }

    #pragma unroll
    for (int mi = 0; mi < 4; mi++) {
        int rowA = m0 + wm + mi*16 + qr;
        int rowB = rowA + 8;
        #pragma unroll
        for (int ni = 0; ni < 4; ni++) {
            int col = n0 + wn + ni*8 + qc*2;
            float b0v = bias[col], b1v = bias[col+1];
            float vx = acc[mi][ni].x + b0v, vy = acc[mi][ni].y + b1v;
            float vz = acc[mi][ni].z + b0v, vw = acc[mi][ni].w + b1v;
            if (EPI == 0) {
                int part = col / DIM, cc = col - part*DIM;
                __half* dst = (part == 0) ? g_qh : (part == 1) ? g_kh : g_vh;
                int h = cc >> 6, d = cc & 63;
                long hb = ((long)b*HEADS + h)*NTOK;
                if (rowA < M) *(__half2*)&dst[(hb + rowA)*HD + d] = __floats2half2_rn(vx, vy);
                if (rowB < M) *(__half2*)&dst[(hb + rowB)*HD + d] = __floats2half2_rn(vz, vw);
            } else if (EPI == 1) {
                if (rowA < M) {
                    long o = ((long)b*NTOK + g_eidx[b*NTOK + rowA])*DIM + col;
                    *(float2*)&dout[o] = make_float2(vx + xfull[o], vy + xfull[o+1]);
                }
                if (rowB < M) {
                    long o = ((long)b*NTOK + g_eidx[b*NTOK + rowB])*DIM + col;
                    *(float2*)&dout[o] = make_float2(vz + xfull[o], vw + xfull[o+1]);
                }
            } else if (EPI == 2) {
                if (rowA < M) *(__half2*)&g_h1[((long)b*NTOK + rowA)*HID + col] =
                    __floats2half2_rn(gelu_exact(gelu_exact(vx)), gelu_exact(gelu_exact(vy)));
                if (rowB < M) *(__half2*)&g_h1[((long)b*NTOK + rowB)*HID + col] =
                    __floats2half2_rn(gelu_exact(gelu_exact(vz)), gelu_exact(gelu_exact(vw)));
            } else {
                if (rowA < M) *(float2*)&g_h2[((long)b*NTOK + rowA)*DIM + col] = make_float2(vx, vy);
                if (rowB < M) *(float2*)&g_h2[((long)b*NTOK + rowB)*DIM + col] = make_float2(vz, vw);
            }
        }
    }
    #undef AS
    #undef BS
}

// ---------------- fp16 flash attention: KT=64, 4-stage ring, wait_group 2 ----------------
#define KT 64
#define ATTN_SMEM (4*KT*72*2*2)   // 73728 B

__global__ void __launch_bounds__(256) k_attn() {
    int b = blockIdx.z, h = blockIdx.y;
    int M = g_cntE[b];
    int m0 = blockIdx.x * 128;
    if (m0 >= M) return;
    int tid = threadIdx.x, w = tid >> 5, lane = tid & 31;
    int qr = lane >> 2, qc = lane & 3;
    long base = ((long)b*HEADS + h)*NTOK*HD;

    extern __shared__ __align__(16) __half sma[];
    __half* Ks_ = sma;              // 4 x 64 x 72
    __half* Vs_ = sma + 4*KT*72;
    #define KS(bf,r,c) Ks_[(bf)*(KT*72) + (r)*72 + (c)]
    #define VS(bf,r,c) Vs_[(bf)*(KT*72) + (r)*72 + (c)]

    int r0 = m0 + w*16 + qr, r1 = r0 + 8;
    bool v0 = r0 < M, v1 = r1 < M;
    const __half* q0p = g_qh + base + (long)r0*HD;
    const __half* q1p = g_qh + base + (long)r1*HD;
    unsigned qf[4][4];
    #pragma unroll
    for (int ks = 0; ks < 4; ks++) {
        int c = ks*16 + qc*2;
        qf[ks][0] = v0 ? *(const unsigned*)&q0p[c]   : 0u;
        qf[ks][1] = v1 ? *(const unsigned*)&q1p[c]   : 0u;
        qf[ks][2] = v0 ? *(const unsigned*)&q0p[c+8] : 0u;
        qf[ks][3] = v1 ? *(const unsigned*)&q1p[c+8] : 0u;
    }

    auto issue = [&](int kb, int bf) {
        #pragma unroll
        for (int t = 0; t < 4; t++) {
            int task = tid + 256*t;            // 0..1023
            int mat  = task >> 9;
            int t2   = task & 511;
            int row  = t2 >> 3;
            int c8   = (t2 & 7) * 8;
            bool ok = (kb + row) < M;
            const __half* src = (mat ? g_vh : g_kh) + base + (long)(kb + (ok ? row : 0))*HD + c8;
            if (mat) cpa16z(&VS(bf, row, c8), src, ok);
            else     cpa16z(&KS(bf, row, c8), src, ok);
        }
    };

    float4 oacc[8];
    #pragma unroll
    for (int i = 0; i < 8; i++) oacc[i] = make_float4(0,0,0,0);
    float mx0 = -1e30f, mx1 = -1e30f, l0 = 0.0f, l1 = 0.0f;
    const float SC = 0.125f * 1.44269504088896340736f;

    int ntiles = (M + KT - 1) / KT;
    issue(0, 0); cpa_commit();
    if (ntiles > 1) issue(KT, 1);
    cpa_commit();
    if (ntiles > 2) issue(2*KT, 2);
    cpa_commit();

    int bf = 0;
    #pragma unroll 1
    for (int kt = 0; kt < ntiles; kt++) {
        int kb = kt * KT;
        cpa_wait2();
        __syncthreads();

        float4 s[8];
        #pragma unroll
        for (int nt = 0; nt < 8; nt++) s[nt] = make_float4(0,0,0,0);
        #pragma unroll
        for (int dh = 0; dh < 2; dh++) {
            #pragma unroll
            for (int nt = 0; nt < 8; nt++) {
                unsigned kf[4];
                ldsm4(kf, &KS(bf, nt*8 + (lane & 7), (lane >> 3)*8 + dh*32));
                mma16(s[nt], qf[dh*2],     kf[0], kf[1]);
                mma16(s[nt], qf[dh*2 + 1], kf[2], kf[3]);
            }
        }
        float t0 = -1e30f, t1 = -1e30f;
        #pragma unroll
        for (int nt = 0; nt < 8; nt++) {
            s[nt].x *= SC; s[nt].y *= SC; s[nt].z *= SC; s[nt].w *= SC;
            int c0 = kb + nt*8 + qc*2;
            if (c0     >= M) { s[nt].x = -1e30f; s[nt].z = -1e30f; }
            if (c0 + 1 >= M) { s[nt].y = -1e30f; s[nt].w = -1e30f; }
            t0 = fmaxf(t0, fmaxf(s[nt].x, s[nt].y));
            t1 = fmaxf(t1, fmaxf(s[nt].z, s[nt].w));
        }
        t0 = fmaxf(t0, __shfl_xor_sync(0xffffffffu, t0, 1));
        t0 = fmaxf(t0, __shfl_xor_sync(0xffffffffu, t0, 2));
        t1 = fmaxf(t1, __shfl_xor_sync(0xffffffffu, t1, 1));
        t1 = fmaxf(t1, __shfl_xor_sync(0xffffffffu, t1, 2));
        float nm0 = fmaxf(mx0, t0), nm1 = fmaxf(mx1, t1);
        bool nochg = (nm0 == mx0) && (nm1 == mx1);
        if (!__all_sync(0xffffffffu, nochg)) {
            float cr0 = ex2(mx0 - nm0), cr1 = ex2(mx1 - nm1);
            l0 *= cr0; l1 *= cr1;
            #pragma unroll
            for (int i = 0; i < 8; i++) {
                oacc[i].x *= cr0; oacc[i].y *= cr0;
                oacc[i].z *= cr1; oacc[i].w *= cr1;
            }
        }
        mx0 = nm0; mx1 = nm1;

        float ps0 = 0.0f, ps1 = 0.0f;
        unsigned pa[4][4];
        #pragma unroll
        for (int nt = 0; nt < 8; nt++) {
            float px = ex2(s[nt].x - mx0), py = ex2(s[nt].y - mx0);
            float pz = ex2(s[nt].z - mx1), pw = ex2(s[nt].w - mx1);
            ps0 += px + py; ps1 += pz + pw;
            int ks = nt >> 1, hi = (nt & 1) * 2;
            pa[ks][hi]     = h2u(__floats2half2_rn(px, py));
            pa[ks][hi + 1] = h2u(__floats2half2_rn(pz, pw));
        }
        ps0 += __shfl_xor_sync(0xffffffffu, ps0, 1);
        ps0 += __shfl_xor_sync(0xffffffffu, ps0, 2);
        ps1 += __shfl_xor_sync(0xffffffffu, ps1, 1);
        ps1 += __shfl_xor_sync(0xffffffffu, ps1, 2);
        l0 += ps0; l1 += ps1;

        #pragma unroll
        for (int ks = 0; ks < 4; ks++) {
            unsigned vf[4][4];
            #pragma unroll
            for (int dp = 0; dp < 4; dp++)
                ldsm4t(vf[dp], &VS(bf, 16*ks + ((lane >> 3) & 1)*8 + (lane & 7),
                                   dp*16 + (lane >> 4)*8));
            #pragma unroll
            for (int nt = 0; nt < 8; nt++)
                mma16(oacc[nt], pa[ks], vf[nt >> 1][(nt & 1)*2], vf[nt >> 1][(nt & 1)*2 + 1]);
        }

        if (kt + 3 < ntiles) {
            int nb = bf + 3; if (nb >= 4) nb -= 4;
            issue(kb + 3*KT, nb);
        }
        cpa_commit();
        if (++bf == 4) bf = 0;
    }

    float inv0 = 1.0f / l0, inv1 = 1.0f / l1;
    #pragma unroll
    for (int nt = 0; nt < 8; nt++) {
        int col = h*64 + nt*8 + qc*2;
        if (v0) *(__half2*)&g_oh[((long)b*NTOK + r0)*DIM + col] =
            __floats2half2_rn(oacc[nt].x * inv0, oacc[nt].y * inv0);
        if (v1) *(__half2*)&g_oh[((long)b*NTOK + r1)*DIM + col] =
            __floats2half2_rn(oacc[nt].z * inv1, oacc[nt].w * inv1);
    }
    #undef KS
    #undef VS
}

// ---------------- LayerNorm on easy rows (fp16 out) ----------------
__global__ void k_ln(const float* __restrict__ x, const float* __restrict__ g,
                     const float* __restrict__ be) {
    int b = blockIdx.y, m = blockIdx.x;
    if (m >= g_cntZ[b]) return;
    int tok = g_zidx[b*NTOK + m];
    const float* row = x + ((long)b*NTOK + tok)*DIM;
    int tid = threadIdx.x;
    float v[3];
    float s = 0.0f, s2 = 0.0f;
    #pragma unroll
    for (int i = 0; i < 3; i++) {
        v[i] = row[tid + i*256];
        s += v[i]; s2 += v[i]*v[i];
    }
    __shared__ float r0[256], r1[256];
    r0[tid] = s; r1[tid] = s2;
    __syncthreads();
    for (int off = 128; off; off >>= 1) {
        if (tid < off) { r0[tid] += r0[tid+off]; r1[tid] += r1[tid+off]; }
        __syncthreads();
    }
    float mu  = r0[0] * (1.0f/DIM);
    float var = r1[0] * (1.0f/DIM) - mu*mu;
    float rs  = rsqrtf(var + 1e-5f);
    __half* outp = g_hln + ((long)b*NTOK + m)*DIM;
    #pragma unroll
    for (int i = 0; i < 3; i++) {
        int c = tid + i*256;
        outp[c] = __float2half_rn((v[i] - mu) * rs * g[c] + be[c]);
    }
}

// ---------------- 2-stage masked mean pool + fused ECA ----------------
__global__ void k_pool1() {
    int b = blockIdx.z, part = blockIdx.y;
    int c = blockIdx.x * 256 + threadIdx.x;
    int cz = g_cntZ[b];
    int chunk = (cz + 15) / 16;
    int mlo = part * chunk, mhi = min(mlo + chunk, cz);
    float s = 0.0f;
    for (int m = mlo; m < mhi; m++) s += g_h2[((long)b*NTOK + m)*DIM + c];
    g_poolp[(b*16 + part)*DIM + c] = s;
}

__global__ void k_pool2(const float* __restrict__ w) {
    int b = blockIdx.x, c = threadIdx.x;
    __shared__ float pooled[DIM];
    float s = 0.0f;
    #pragma unroll
    for (int p = 0; p < 16; p++) s += g_poolp[(b*16 + p)*DIM + c];
    pooled[c] = s / fmaxf((float)g_cntZ[b], 1.0f);
    __syncthreads();
    float g = 0.0f;
    #pragma unroll
    for (int tt = 0; tt < 5; tt++) {
        int cc = c + tt - 2;
        if (cc >= 0 && cc < DIM) g += w[tt] * pooled[cc];
    }
    g_sig[b*DIM + c] = 1.0f / (1.0f + __expf(-g));
}

// ---------------- LTRM scatter ----------------
__global__ void k_ltrm(const float* __restrict__ x, float* __restrict__ out) {
    int b = blockIdx.y, m = blockIdx.x;
    if (m >= g_cntZ[b]) return;
    int tok = g_zidx[b*NTOK + m];
    long ro = ((long)b*NTOK + tok)*DIM;
    long ri = ((long)b*NTOK + m)*DIM;
    for (int c = threadIdx.x; c < DIM; c += 256)
        out[ro + c] = x[ro + c] + g_h2[ri + c] * g_sig[b*DIM + c];
}

// ---------------- launch ----------------
extern "C" void kernel_launch(void* const* d_in, const int* in_sizes, int n_in,
                              void* d_out, int out_size) {
    const float* x      = (const float*)d_in[0];
    const float* hint   = (const float*)d_in[1];
    const float* qkv_w  = (const float*)d_in[2];
    const float* qkv_b  = (const float*)d_in[3];
    const float* proj_w = (const float*)d_in[4];
    const float* proj_b = (const float*)d_in[5];
    const float* ln_g   = (const float*)d_in[6];
    const float* ln_b   = (const float*)d_in[7];
    const float* fc1_w  = (const float*)d_in[8];
    const float* fc1_b  = (const float*)d_in[9];
    const float* fc2_w  = (const float*)d_in[10];
    const float* fc2_b  = (const float*)d_in[11];
    const float* eca_w  = (const float*)d_in[12];
    float* out = (float*)d_out;

    __half *d_xh, *d_wqkv, *d_wproj, *d_wfc1, *d_wfc2, *d_oh, *d_hln, *d_h1;
    cudaGetSymbolAddress((void**)&d_xh,   g_xh);
    cudaGetSymbolAddress((void**)&d_wqkv, g_wqkv);
    cudaGetSymbolAddress((void**)&d_wproj,g_wproj);
    cudaGetSymbolAddress((void**)&d_wfc1, g_wfc1);
    cudaGetSymbolAddress((void**)&d_wfc2, g_wfc2);
    cudaGetSymbolAddress((void**)&d_oh,  g_oh);
    cudaGetSymbolAddress((void**)&d_hln, g_hln);
    cudaGetSymbolAddress((void**)&d_h1,  g_h1);

    static bool attr_done = false;
    if (!attr_done) {
        cudaFuncSetAttribute(k_gemm<0>, cudaFuncAttributeMaxDynamicSharedMemorySize, GEMM_SMEM);
        cudaFuncSetAttribute(k_gemm<1>, cudaFuncAttributeMaxDynamicSharedMemorySize, GEMM_SMEM);
        cudaFuncSetAttribute(k_gemm<2>, cudaFuncAttributeMaxDynamicSharedMemorySize, GEMM_SMEM);
        cudaFuncSetAttribute(k_gemm<3>, cudaFuncAttributeMaxDynamicSharedMemorySize, GEMM_SMEM);
        cudaFuncSetAttribute(k_attn,    cudaFuncAttributeMaxDynamicSharedMemorySize, ATTN_SMEM);
        attr_done = true;
    }

    cudaStream_t s2;
    cudaStreamCreateWithFlags(&s2, cudaStreamNonBlocking);
    cudaEvent_t e0, eCvt, eCompact, eEasy;
    cudaEventCreateWithFlags(&e0,       cudaEventDisableTiming);
    cudaEventCreateWithFlags(&eCvt,     cudaEventDisableTiming);
    cudaEventCreateWithFlags(&eCompact, cudaEventDisableTiming);
    cudaEventCreateWithFlags(&eEasy,    cudaEventDisableTiming);

    cudaEventRecord(e0, 0);
    cudaStreamWaitEvent(s2, e0, 0);
    k_cvtall<<<5376, 256, 0, s2>>>(x, qkv_w, proj_w, fc1_w, fc2_w);
    cudaEventRecord(eCvt, s2);

    k_edge   <<<BB*NTOK/8, 256>>>(hint);
    k_compact<<<BB, 1024>>>();
    cudaEventRecord(eCompact, 0);

    // edge path on stream0
    cudaStreamWaitEvent(0, eCvt, 0);
    k_gemm<0><<<dim3(3*DIM/128, NTOK/128, BB), 256, GEMM_SMEM>>>(x, d_xh, d_wqkv, qkv_b, out);
    k_attn   <<<dim3(NTOK/128, HEADS, BB), 256, ATTN_SMEM>>>();
    k_gemm<1><<<dim3(DIM/128, NTOK/128, BB), 256, GEMM_SMEM>>>(x, d_oh, d_wproj, proj_b, out);

    // easy path on s2
    cudaStreamWaitEvent(s2, eCompact, 0);
    k_ln     <<<dim3(NTOK, BB), 256, 0, s2>>>(x, ln_g, ln_b);
    k_gemm<2><<<dim3(HID/128, NTOK/128, BB), 256, GEMM_SMEM, s2>>>(x, d_hln, d_wfc1, fc1_b, out);
    k_gemm<3><<<dim3(DIM/128, NTOK/128, BB), 256, GEMM_SMEM, s2>>>(x, d_h1, d_wfc2, fc2_b, out);
    k_pool1  <<<dim3(DIM/256, 16, BB), 256, 0, s2>>>();
    k_pool2  <<<BB, DIM, 0, s2>>>(eca_w);
    k_ltrm   <<<dim3(NTOK, BB), 256, 0, s2>>>(x, out);
    cudaEventRecord(eEasy, s2);

    cudaStreamWaitEvent(0, eEasy, 0);

    cudaEventDestroy(e0);
    cudaEventDestroy(eCvt);
    cudaEventDestroy(eCompact);
    cudaEventDestroy(eEasy);
    cudaStreamDestroy(s2);
}